// round 12
// baseline (speedup 1.0000x reference)
#include <cuda_runtime.h>
#include <cuda_bf16.h>
#include <cstddef>
#include <cstdint>

// Problem constants
#define BB 512
#define TT 256
#define DD 128
#define HH 128
#define SS 32
#define BT (BB*TT)   // 131072

typedef unsigned long long u64;
typedef uint32_t u32;

// ---------------------------------------------------------------------------
// f32x2 packed-math helpers
// ---------------------------------------------------------------------------
__device__ __forceinline__ u64 ffma2(u64 a, u64 b, u64 c) {
    u64 d;
    asm("fma.rn.f32x2 %0, %1, %2, %3;" : "=l"(d) : "l"(a), "l"(b), "l"(c));
    return d;
}
__device__ __forceinline__ u64 add2(u64 a, u64 b) {
    u64 d;
    asm("add.rn.f32x2 %0, %1, %2;" : "=l"(d) : "l"(a), "l"(b));
    return d;
}
__device__ __forceinline__ u64 pack2(float v) {
    u64 d;
    asm("mov.b64 %0, {%1, %1};" : "=l"(d) : "f"(v));
    return d;
}
__device__ __forceinline__ u64 packab(float a, float b) {
    u64 d;
    asm("mov.b64 %0, {%1, %2};" : "=l"(d) : "f"(a), "f"(b));
    return d;
}
__device__ __forceinline__ float2 unpk(u64 x) {
    float2 f;
    asm("mov.b64 {%0, %1}, %2;" : "=f"(f.x), "=f"(f.y) : "l"(x));
    return f;
}
union F4U2 { float4 f; u64 u[2]; };

// ---------------------------------------------------------------------------
// Device-global scratch
// ---------------------------------------------------------------------------
__device__ float g_Xz[(size_t)BT * HH];
__device__ float g_Xr[(size_t)BT * HH];
__device__ float g_Xh[(size_t)BT * HH];
__device__ float g_gh[(size_t)BT * HH];
// bf16 hi/lo weight copies, layout [j][d], order:
// 0=W_z 1=V_z 2=W_r 3=V_r 4=W_h 5=V_h 6=W_dg_h
__device__ __nv_bfloat16 g_Wbh[7 * 16384];
__device__ __nv_bfloat16 g_Wbl[7 * 16384];

__global__ void noop_kernel() {}

// ---------------------------------------------------------------------------
// Kernel 0: convert 7 weight matrices fp32 -> bf16 hi/lo
// ---------------------------------------------------------------------------
__global__ void convert_w(const float* __restrict__ Wz, const float* __restrict__ Vz,
                          const float* __restrict__ Wr, const float* __restrict__ Vr,
                          const float* __restrict__ Wh, const float* __restrict__ Vh,
                          const float* __restrict__ Wdgh)
{
    const float* srcs[7] = {Wz, Vz, Wr, Vr, Wh, Vh, Wdgh};
    const float* s = srcs[blockIdx.x];
    __nv_bfloat16* dh = g_Wbh + blockIdx.x * 16384;
    __nv_bfloat16* dl = g_Wbl + blockIdx.x * 16384;
    for (int idx = threadIdx.x; idx < 16384; idx += blockDim.x) {
        float v = s[idx];
        __nv_bfloat16 h = __float2bfloat16(v);
        dh[idx] = h;
        dl[idx] = __float2bfloat16(v - __bfloat162float(h));
    }
}

// ---------------------------------------------------------------------------
// Kernel 1: precompute via warp-level mma.sync (unchanged from R11)
// ---------------------------------------------------------------------------
#define PA 136
#define PANEL_B (128 * PA * 2)
#define SM_BIAS  0
#define SM_AHI   512
#define SM_ALO   (SM_AHI + PANEL_B)
#define SM_MBF   (SM_ALO + PANEL_B)
#define SM_WHI   (SM_MBF + PANEL_B)
#define SM_WLO   (SM_WHI + PANEL_B)
#define SM_TOTAL (SM_WLO + PANEL_B)

__device__ __forceinline__ void mma_bf16(float c[4], u32 a0, u32 a1, u32 a2, u32 a3,
                                         u32 b0, u32 b1) {
    asm("mma.sync.aligned.m16n8k16.row.col.f32.bf16.bf16.f32 "
        "{%0,%1,%2,%3}, {%4,%5,%6,%7}, {%8,%9}, {%0,%1,%2,%3};"
        : "+f"(c[0]), "+f"(c[1]), "+f"(c[2]), "+f"(c[3])
        : "r"(a0), "r"(a1), "r"(a2), "r"(a3), "r"(b0), "r"(b1));
}
__device__ __forceinline__ void ldsm4(u32& r0, u32& r1, u32& r2, u32& r3, u32 a) {
    asm volatile("ldmatrix.sync.aligned.m8n8.x4.shared.b16 {%0,%1,%2,%3}, [%4];"
                 : "=r"(r0), "=r"(r1), "=r"(r2), "=r"(r3) : "r"(a));
}

__device__ __forceinline__ void gpass(const __nv_bfloat16* __restrict__ A,
                                      const __nv_bfloat16* __restrict__ W,
                                      float acc[2][8][4], int row0, int col0, int lane)
{
    const int ar = lane & 15, ac = (lane >> 4) << 3;
    const int bj = ((lane >> 4) << 3) + (lane & 7);
    const int bk = ((lane >> 3) & 1) << 3;
    #pragma unroll
    for (int kt = 0; kt < 8; kt++) {
        const int k0 = kt * 16;
        u32 a[2][4];
        #pragma unroll
        for (int mt = 0; mt < 2; mt++) {
            u32 ad = (u32)__cvta_generic_to_shared(A + (row0 + mt * 16 + ar) * PA + k0 + ac);
            ldsm4(a[mt][0], a[mt][1], a[mt][2], a[mt][3], ad);
        }
        u32 b[4][4];
        #pragma unroll
        for (int np = 0; np < 4; np++) {
            u32 bd = (u32)__cvta_generic_to_shared(W + (col0 + np * 16 + bj) * PA + k0 + bk);
            ldsm4(b[np][0], b[np][1], b[np][2], b[np][3], bd);
        }
        #pragma unroll
        for (int mt = 0; mt < 2; mt++)
            #pragma unroll
            for (int nt = 0; nt < 8; nt++)
                mma_bf16(acc[mt][nt], a[mt][0], a[mt][1], a[mt][2], a[mt][3],
                         b[nt >> 1][(nt & 1) * 2], b[nt >> 1][(nt & 1) * 2 + 1]);
    }
}

__device__ __forceinline__ void stage_w(char* smem, int off, const __nv_bfloat16* g) {
    const uint4* src = (const uint4*)g;
    #pragma unroll
    for (int it = 0; it < 8; it++) {
        int cc = threadIdx.x + it * 256;
        int j = cc >> 4, k8 = (cc & 15) * 8;
        *(uint4*)(smem + off + (j * PA + k8) * 2) = src[cc];
    }
}

__global__ __launch_bounds__(256, 1)
void precompute_mma(const float* __restrict__ x,     const float* __restrict__ mask,
                    const float* __restrict__ delta, const float* __restrict__ xlast,
                    const float* __restrict__ x_mean,
                    const float* __restrict__ w_dg_x, const float* __restrict__ b_dg_x,
                    const float* __restrict__ b_dg_h,
                    const float* __restrict__ b_z, const float* __restrict__ b_r,
                    const float* __restrict__ b_h)
{
    extern __shared__ char smem[];
    float* bias_s = (float*)(smem + SM_BIAS);
    __nv_bfloat16* Ahi = (__nv_bfloat16*)(smem + SM_AHI);
    __nv_bfloat16* Alo = (__nv_bfloat16*)(smem + SM_ALO);
    __nv_bfloat16* Mbf = (__nv_bfloat16*)(smem + SM_MBF);
    __nv_bfloat16* Whi = (__nv_bfloat16*)(smem + SM_WHI);
    __nv_bfloat16* Wlo = (__nv_bfloat16*)(smem + SM_WLO);

    const int tid  = threadIdx.x;
    const int lane = tid & 31;
    const int wrp  = tid >> 5;
    const int row0 = (wrp & 3) * 32;
    const int col0 = (wrp >> 2) * 64;
    const int brow = blockIdx.x * 128;
    const int b    = brow >> 8;
    const int g = lane >> 2, t = lane & 3;

    float acc[2][8][4];

    for (int idx = tid; idx < 128 * 128; idx += 256) {
        int r = idx >> 7, d = idx & 127;
        float v = delta[(size_t)(brow + r) * DD + d];
        __nv_bfloat16 hi = __float2bfloat16(v);
        Ahi[r * PA + d] = hi;
        Alo[r * PA + d] = __float2bfloat16(v - __bfloat162float(hi));
    }
    stage_w(smem, SM_WHI, g_Wbh + 6 * 16384);
    stage_w(smem, SM_WLO, g_Wbl + 6 * 16384);
    if (tid < 128) bias_s[tid] = b_dg_h[tid];
    __syncthreads();

    #pragma unroll
    for (int mt = 0; mt < 2; mt++)
        #pragma unroll
        for (int nt = 0; nt < 8; nt++)
            #pragma unroll
            for (int q = 0; q < 4; q++) acc[mt][nt][q] = 0.0f;
    {
        const __nv_bfloat16* Ap[3] = {Ahi, Ahi, Alo};
        const __nv_bfloat16* Wp[3] = {Whi, Wlo, Whi};
        #pragma unroll 1
        for (int p = 0; p < 3; p++) gpass(Ap[p], Wp[p], acc, row0, col0, lane);
    }
    #pragma unroll
    for (int mt = 0; mt < 2; mt++)
        #pragma unroll
        for (int nt = 0; nt < 8; nt++) {
            int j0 = col0 + nt * 8 + 2 * t;
            float2 bv = *(const float2*)&bias_s[j0];
            size_t r0g = (size_t)(brow + row0 + mt * 16 + g) * HH + j0;
            size_t r8g = r0g + (size_t)8 * HH;
            *(float2*)&g_gh[r0g] = make_float2(__expf(-fmaxf(acc[mt][nt][0] + bv.x, 0.0f)),
                                               __expf(-fmaxf(acc[mt][nt][1] + bv.y, 0.0f)));
            *(float2*)&g_gh[r8g] = make_float2(__expf(-fmaxf(acc[mt][nt][2] + bv.x, 0.0f)),
                                               __expf(-fmaxf(acc[mt][nt][3] + bv.y, 0.0f)));
        }
    __syncthreads();

    for (int idx = tid; idx < 128 * 128; idx += 256) {
        int r = idx >> 7, d = idx & 127;
        size_t gg = (size_t)(brow + r) * DD + d;
        float xv = x[gg], mv = mask[gg], dl = delta[gg], xl = xlast[gg];
        float gx = __expf(-fmaxf(fmaf(w_dg_x[d], dl, b_dg_x[d]), 0.0f));
        float xm = x_mean[b * DD + d];
        float xh = mv * xv + (1.0f - mv) * (gx * xl + (1.0f - gx) * xm);
        __nv_bfloat16 hi = __float2bfloat16(xh);
        Ahi[r * PA + d] = hi;
        Alo[r * PA + d] = __float2bfloat16(xh - __bfloat162float(hi));
        Mbf[r * PA + d] = __float2bfloat16(mv);
    }
    __syncthreads();

    const int wi[3] = {0, 2, 4};
    const int vi[3] = {1, 3, 5};
    const float* biases[3] = {b_z, b_r, b_h};
    float* outs[3] = {g_Xz, g_Xr, g_Xh};

    #pragma unroll 1
    for (int gate = 0; gate < 3; gate++) {
        stage_w(smem, SM_WHI, g_Wbh + wi[gate] * 16384);
        stage_w(smem, SM_WLO, g_Wbl + wi[gate] * 16384);
        if (tid < 128) bias_s[tid] = biases[gate][tid];
        __syncthreads();

        #pragma unroll
        for (int mt = 0; mt < 2; mt++)
            #pragma unroll
            for (int nt = 0; nt < 8; nt++)
                #pragma unroll
                for (int q = 0; q < 4; q++) acc[mt][nt][q] = 0.0f;

        const __nv_bfloat16* Ap[5] = {Ahi, Ahi, Alo, Mbf, Mbf};
        const __nv_bfloat16* Wp[5] = {Whi, Wlo, Whi, Whi, Wlo};
        #pragma unroll 1
        for (int p = 0; p < 5; p++) {
            if (p == 3) {
                __syncthreads();
                stage_w(smem, SM_WHI, g_Wbh + vi[gate] * 16384);
                stage_w(smem, SM_WLO, g_Wbl + vi[gate] * 16384);
                __syncthreads();
            }
            gpass(Ap[p], Wp[p], acc, row0, col0, lane);
        }

        float* obase = outs[gate];
        #pragma unroll
        for (int mt = 0; mt < 2; mt++)
            #pragma unroll
            for (int nt = 0; nt < 8; nt++) {
                int j0 = col0 + nt * 8 + 2 * t;
                float2 bv = *(const float2*)&bias_s[j0];
                size_t r0g = (size_t)(brow + row0 + mt * 16 + g) * HH + j0;
                size_t r8g = r0g + (size_t)8 * HH;
                *(float2*)&obase[r0g] = make_float2(acc[mt][nt][0] + bv.x, acc[mt][nt][1] + bv.y);
                *(float2*)&obase[r8g] = make_float2(acc[mt][nt][2] + bv.x, acc[mt][nt][3] + bv.y);
            }
        __syncthreads();
    }
}

// ---------------------------------------------------------------------------
// Kernel 2: recurrence, gate-specialized with U in registers. 128 CTAs x 256.
// h0 (tid<128): full Uz in regs -> complete z gate; owns h state + update.
// h1: full Ur in regs -> complete r gate; publishes r*h.
// h_tilde: split-k, Uh from smem, partials via xchH. 3 barriers per step.
// ---------------------------------------------------------------------------
#define PUS 129
#define OFS_UZ  0                         // staging [k][j] pitch 129: 16512 fl
#define OFS_UR  16512
#define OFS_UH2 33024                     // float2 [kp][j]: 16384 fl
#define OFS_HT  (OFS_UH2 + 16384)         // 49408: float[512]
#define OFS_RHT (OFS_HT + 512)            // 49920: float[512]
#define OFS_XH  (OFS_RHT + 512)           // 50432: u64[256] = 512 fl
#define SMEMB_FL (OFS_XH + 512)           // 50944 fl = 203776 B

__global__ __launch_bounds__(256, 1)
void recurrent_kernel(const float* __restrict__ hs0,
                      const float* __restrict__ Uz, const float* __restrict__ Ur,
                      const float* __restrict__ Uh,
                      const float* __restrict__ statics,
                      const float* __restrict__ W_out, const float* __restrict__ b_out,
                      float* __restrict__ out)
{
    extern __shared__ float sm[];
    float*  UzS  = sm + OFS_UZ;               // [k][j] pitch 129 (staging)
    float*  UrS  = sm + OFS_UR;
    float2* Uh2  = (float2*)(sm + OFS_UH2);   // [kp][j]
    float*  hT   = sm + OFS_HT;               // [j][4 rows]
    float*  rhT  = sm + OFS_RHT;
    u64*    xchH = (u64*)(sm + OFS_XH);       // [j][2]: h01,h23

    const int tid  = threadIdx.x;
    const int j    = tid & 127;
    const bool h0  = tid < 128;
    const int kq0  = h0 ? 0 : 32;             // kp range for h_tilde
    const int b0   = blockIdx.x * 4;

    // stage U into smem (coalesced gmem reads, conflict-free smem writes)
    for (int idx = tid; idx < HH * HH; idx += 256) {
        int jj = idx >> 7, k = idx & 127;
        UzS[k * PUS + jj] = Uz[idx];
        UrS[k * PUS + jj] = Ur[idx];
    }
    for (int idx = tid; idx < 64 * 128; idx += 256) {
        int kp = idx >> 7, jj = idx & 127;
        Uh2[kp * 128 + jj] = make_float2(Uh[jj * 128 + 2 * kp],
                                         Uh[jj * 128 + 2 * kp + 1]);
    }

    float hreg[4], cG[4], cXz[4], cXr[4], cXh[4], zg[4];
    if (h0) {
        #pragma unroll
        for (int r = 0; r < 4; r++) {
            hreg[r] = hs0[(b0 + r) * HH + j];
            int g = ((b0 + r) * TT) * HH + j;
            cG[r] = g_gh[g]; cXz[r] = g_Xz[g]; cXh[r] = g_Xh[g];
        }
    } else {
        #pragma unroll
        for (int r = 0; r < 4; r++)
            cXr[r] = g_Xr[((b0 + r) * TT) * HH + j];
    }
    __syncthreads();

    // this half's full-k U slice into registers:
    // h0 -> Uz (z gate), h1 -> Ur (r gate)
    const float* Usel = h0 ? UzS : UrS;
    float ureg[128];
    #pragma unroll
    for (int k = 0; k < 128; k++)
        ureg[k] = Usel[k * PUS + j];

    u64 sh01 = 0, sh23 = 0;   // snapshot of current step's Xh seeds

    #pragma unroll 1
    for (int t = 0; t < TT; t++) {
        if (h0) {
            #pragma unroll
            for (int r = 0; r < 4; r++) hreg[r] *= cG[r];
            *(float4*)&hT[j * 4] = make_float4(hreg[0], hreg[1], hreg[2], hreg[3]);
        }
        __syncthreads();   // B1: hT published

        if (h0) {
            // ---- z gate: full k, Uz from registers ----
            u64 az01 = packab(cXz[0], cXz[1]);
            u64 az23 = packab(cXz[2], cXz[3]);
            sh01 = packab(cXh[0], cXh[1]);
            sh23 = packab(cXh[2], cXh[3]);
            if (t + 1 < TT) {
                #pragma unroll
                for (int r = 0; r < 4; r++) {
                    int g = ((b0 + r) * TT + t + 1) * HH + j;
                    cG[r] = g_gh[g]; cXz[r] = g_Xz[g]; cXh[r] = g_Xh[g];
                }
            }
            #pragma unroll
            for (int k = 0; k < 128; k++) {
                F4U2 hv; hv.f = *(const float4*)&hT[k * 4];
                u64 u2 = pack2(ureg[k]);
                az01 = ffma2(hv.u[0], u2, az01);
                az23 = ffma2(hv.u[1], u2, az23);
            }
            float2 s01 = unpk(az01), s23 = unpk(az23);
            zg[0] = 1.0f / (1.0f + __expf(-s01.x));
            zg[1] = 1.0f / (1.0f + __expf(-s01.y));
            zg[2] = 1.0f / (1.0f + __expf(-s23.x));
            zg[3] = 1.0f / (1.0f + __expf(-s23.y));
        } else {
            // ---- r gate: full k, Ur from registers; publish r*h ----
            u64 ar01 = packab(cXr[0], cXr[1]);
            u64 ar23 = packab(cXr[2], cXr[3]);
            if (t + 1 < TT) {
                #pragma unroll
                for (int r = 0; r < 4; r++)
                    cXr[r] = g_Xr[((b0 + r) * TT + t + 1) * HH + j];
            }
            #pragma unroll
            for (int k = 0; k < 128; k++) {
                F4U2 hv; hv.f = *(const float4*)&hT[k * 4];
                u64 u2 = pack2(ureg[k]);
                ar01 = ffma2(hv.u[0], u2, ar01);
                ar23 = ffma2(hv.u[1], u2, ar23);
            }
            float2 s01 = unpk(ar01), s23 = unpk(ar23);
            float4 hv4 = *(const float4*)&hT[j * 4];
            float rg0 = 1.0f / (1.0f + __expf(-s01.x));
            float rg1 = 1.0f / (1.0f + __expf(-s01.y));
            float rg2 = 1.0f / (1.0f + __expf(-s23.x));
            float rg3 = 1.0f / (1.0f + __expf(-s23.y));
            *(float4*)&rhT[j * 4] = make_float4(rg0 * hv4.x, rg1 * hv4.y,
                                                rg2 * hv4.z, rg3 * hv4.w);
        }
        __syncthreads();   // B2: rhT published

        // ---- h_tilde partials over this half's kp range (Uh from smem) ----
        u64 ah01 = h0 ? sh01 : 0ull;
        u64 ah23 = h0 ? sh23 : 0ull;
        #pragma unroll 8
        for (int kp = kq0; kp < kq0 + 32; kp++) {
            int k4 = kp * 8;
            F4U2 re; re.f = *(const float4*)&rhT[k4];
            F4U2 ro; ro.f = *(const float4*)&rhT[k4 + 4];
            float2 u2 = Uh2[kp * 128 + j];
            u64 uhe = pack2(u2.x), uho = pack2(u2.y);
            ah01 = ffma2(re.u[0], uhe, ah01);
            ah23 = ffma2(re.u[1], uhe, ah23);
            ah01 = ffma2(ro.u[0], uho, ah01);
            ah23 = ffma2(ro.u[1], uho, ah23);
        }
        if (!h0) {
            xchH[2 * j]     = ah01;
            xchH[2 * j + 1] = ah23;
        }
        __syncthreads();   // B3: h_tilde partials exchanged

        if (h0) {
            float2 p01 = unpk(add2(ah01, xchH[2 * j]));
            float2 p23 = unpk(add2(ah23, xchH[2 * j + 1]));
            float pre[4] = {p01.x, p01.y, p23.x, p23.y};
            #pragma unroll
            for (int r = 0; r < 4; r++) {
                float ht = 2.0f / (1.0f + __expf(-2.0f * pre[r])) - 1.0f;
                hreg[r] = (1.0f - zg[r]) * hreg[r] + zg[r] * ht;
            }
        }
    }

    // ---- classifier ----
    __syncthreads();
    if (h0) {
        float wj = W_out[j];
        *(float4*)&hT[j * 4] = make_float4(hreg[0] * wj, hreg[1] * wj,
                                           hreg[2] * wj, hreg[3] * wj);
    }
    __syncthreads();
    for (int s = 64; s > 0; s >>= 1) {
        if (tid < s) {
            float4 a = *(const float4*)&hT[tid * 4];
            float4 c = *(const float4*)&hT[(tid + s) * 4];
            a.x += c.x; a.y += c.y; a.z += c.z; a.w += c.w;
            *(float4*)&hT[tid * 4] = a;
        }
        __syncthreads();
    }
    if (tid < 4) {
        float v = hT[tid];
        float sacc = 0.0f;
        #pragma unroll
        for (int s = 0; s < SS; s++)
            sacc = fmaf(statics[(b0 + tid) * SS + s], W_out[HH + s], sacc);
        out[b0 + tid] = v + sacc + b_out[0];
    }
}

// ---------------------------------------------------------------------------
// Launch
// ---------------------------------------------------------------------------
extern "C" void kernel_launch(void* const* d_in, const int* in_sizes, int n_in,
                              void* d_out, int out_size)
{
    const float* x       = (const float*)d_in[0];
    const float* statics = (const float*)d_in[1];
    const float* mask    = (const float*)d_in[2];
    const float* delta   = (const float*)d_in[3];
    const float* xlast   = (const float*)d_in[4];
    const float* x_mean  = (const float*)d_in[5];
    const float* hs0     = (const float*)d_in[6];
    const float* w_dg_x  = (const float*)d_in[7];
    const float* b_dg_x  = (const float*)d_in[8];
    const float* W_dg_h  = (const float*)d_in[9];
    const float* b_dg_h  = (const float*)d_in[10];
    const float* W_z = (const float*)d_in[11];
    const float* U_z = (const float*)d_in[12];
    const float* V_z = (const float*)d_in[13];
    const float* b_z = (const float*)d_in[14];
    const float* W_r = (const float*)d_in[15];
    const float* U_r = (const float*)d_in[16];
    const float* V_r = (const float*)d_in[17];
    const float* b_r = (const float*)d_in[18];
    const float* W_h = (const float*)d_in[19];
    const float* U_h = (const float*)d_in[20];
    const float* V_h = (const float*)d_in[21];
    const float* b_h = (const float*)d_in[22];
    const float* W_out = (const float*)d_in[23];
    const float* b_out = (const float*)d_in[24];
    float* out = (float*)d_out;

    const int smemB = SMEMB_FL * (int)sizeof(float);   // 203776
    cudaFuncSetAttribute(precompute_mma, cudaFuncAttributeMaxDynamicSharedMemorySize, SM_TOTAL);
    cudaFuncSetAttribute(recurrent_kernel, cudaFuncAttributeMaxDynamicSharedMemorySize, smemB);

    // one no-op: ncu capture (4th launch slot) lands on recurrent_kernel
    noop_kernel<<<1, 32>>>();
    convert_w<<<7, 256>>>(W_z, V_z, W_r, V_r, W_h, V_h, W_dg_h);
    precompute_mma<<<BT / 128, 256, SM_TOTAL>>>(x, mask, delta, xlast, x_mean,
                                                w_dg_x, b_dg_x, b_dg_h, b_z, b_r, b_h);
    recurrent_kernel<<<BB / 4, 256, smemB>>>(hs0, U_z, U_r, U_h,
                                             statics, W_out, b_out, out);
}

// round 13
// speedup vs baseline: 1.2365x; 1.2365x over previous
#include <cuda_runtime.h>
#include <cuda_bf16.h>
#include <cstddef>
#include <cstdint>

// Problem constants
#define BB 512
#define TT 256
#define DD 128
#define HH 128
#define SS 32
#define BT (BB*TT)   // 131072

typedef unsigned long long u64;
typedef uint32_t u32;

// ---------------------------------------------------------------------------
// f32x2 packed-math helpers
// ---------------------------------------------------------------------------
__device__ __forceinline__ u64 ffma2(u64 a, u64 b, u64 c) {
    u64 d;
    asm("fma.rn.f32x2 %0, %1, %2, %3;" : "=l"(d) : "l"(a), "l"(b), "l"(c));
    return d;
}
__device__ __forceinline__ u64 add2(u64 a, u64 b) {
    u64 d;
    asm("add.rn.f32x2 %0, %1, %2;" : "=l"(d) : "l"(a), "l"(b));
    return d;
}
__device__ __forceinline__ u64 pack2(float v) {
    u64 d;
    asm("mov.b64 %0, {%1, %1};" : "=l"(d) : "f"(v));
    return d;
}
__device__ __forceinline__ u64 packab(float a, float b) {
    u64 d;
    asm("mov.b64 %0, {%1, %2};" : "=l"(d) : "f"(a), "f"(b));
    return d;
}
__device__ __forceinline__ float2 unpk(u64 x) {
    float2 f;
    asm("mov.b64 {%0, %1}, %2;" : "=f"(f.x), "=f"(f.y) : "l"(x));
    return f;
}
union F4U2 { float4 f; u64 u[2]; };

// ---------------------------------------------------------------------------
// Device-global scratch
// ---------------------------------------------------------------------------
__device__ float g_Xz[(size_t)BT * HH];
__device__ float g_Xr[(size_t)BT * HH];
__device__ float g_Xh[(size_t)BT * HH];
__device__ float g_gh[(size_t)BT * HH];
// bf16 hi/lo weight copies, layout [j][d], order:
// 0=W_z 1=V_z 2=W_r 3=V_r 4=W_h 5=V_h 6=W_dg_h
__device__ __nv_bfloat16 g_Wbh[7 * 16384];
__device__ __nv_bfloat16 g_Wbl[7 * 16384];

__global__ void noop_kernel() {}

// ---------------------------------------------------------------------------
// Kernel 0: convert 7 weight matrices fp32 -> bf16 hi/lo
// ---------------------------------------------------------------------------
__global__ void convert_w(const float* __restrict__ Wz, const float* __restrict__ Vz,
                          const float* __restrict__ Wr, const float* __restrict__ Vr,
                          const float* __restrict__ Wh, const float* __restrict__ Vh,
                          const float* __restrict__ Wdgh)
{
    const float* srcs[7] = {Wz, Vz, Wr, Vr, Wh, Vh, Wdgh};
    const float* s = srcs[blockIdx.x];
    __nv_bfloat16* dh = g_Wbh + blockIdx.x * 16384;
    __nv_bfloat16* dl = g_Wbl + blockIdx.x * 16384;
    for (int idx = threadIdx.x; idx < 16384; idx += blockDim.x) {
        float v = s[idx];
        __nv_bfloat16 h = __float2bfloat16(v);
        dh[idx] = h;
        dl[idx] = __float2bfloat16(v - __bfloat162float(h));
    }
}

// ---------------------------------------------------------------------------
// Kernel 1: precompute via warp-level mma.sync (HMMA bf16, fp32 accum).
// Merged fragment passes: dual-A (shared B frags) and dual-B (shared A frags).
// ---------------------------------------------------------------------------
#define PA 136
#define PANEL_B (128 * PA * 2)
#define SM_BIAS  0
#define SM_AHI   512
#define SM_ALO   (SM_AHI + PANEL_B)
#define SM_MBF   (SM_ALO + PANEL_B)
#define SM_WHI   (SM_MBF + PANEL_B)
#define SM_WLO   (SM_WHI + PANEL_B)
#define SM_TOTAL (SM_WLO + PANEL_B)

__device__ __forceinline__ void mma_bf16(float c[4], u32 a0, u32 a1, u32 a2, u32 a3,
                                         u32 b0, u32 b1) {
    asm("mma.sync.aligned.m16n8k16.row.col.f32.bf16.bf16.f32 "
        "{%0,%1,%2,%3}, {%4,%5,%6,%7}, {%8,%9}, {%0,%1,%2,%3};"
        : "+f"(c[0]), "+f"(c[1]), "+f"(c[2]), "+f"(c[3])
        : "r"(a0), "r"(a1), "r"(a2), "r"(a3), "r"(b0), "r"(b1));
}
__device__ __forceinline__ void ldsm4(u32& r0, u32& r1, u32& r2, u32& r3, u32 a) {
    asm volatile("ldmatrix.sync.aligned.m8n8.x4.shared.b16 {%0,%1,%2,%3}, [%4];"
                 : "=r"(r0), "=r"(r1), "=r"(r2), "=r"(r3) : "r"(a));
}

// single pass: acc += A @ W^T (warp tile 32 rows x 64 cols)
__device__ __forceinline__ void gpass(const __nv_bfloat16* __restrict__ A,
                                      const __nv_bfloat16* __restrict__ W,
                                      float acc[2][8][4], int row0, int col0, int lane)
{
    const int ar = lane & 15, ac = (lane >> 4) << 3;
    const int bj = ((lane >> 4) << 3) + (lane & 7);
    const int bk = ((lane >> 3) & 1) << 3;
    #pragma unroll
    for (int kt = 0; kt < 8; kt++) {
        const int k0 = kt * 16;
        u32 a[2][4];
        #pragma unroll
        for (int mt = 0; mt < 2; mt++) {
            u32 ad = (u32)__cvta_generic_to_shared(A + (row0 + mt * 16 + ar) * PA + k0 + ac);
            ldsm4(a[mt][0], a[mt][1], a[mt][2], a[mt][3], ad);
        }
        u32 b[4][4];
        #pragma unroll
        for (int np = 0; np < 4; np++) {
            u32 bd = (u32)__cvta_generic_to_shared(W + (col0 + np * 16 + bj) * PA + k0 + bk);
            ldsm4(b[np][0], b[np][1], b[np][2], b[np][3], bd);
        }
        #pragma unroll
        for (int mt = 0; mt < 2; mt++)
            #pragma unroll
            for (int nt = 0; nt < 8; nt++)
                mma_bf16(acc[mt][nt], a[mt][0], a[mt][1], a[mt][2], a[mt][3],
                         b[nt >> 1][(nt & 1) * 2], b[nt >> 1][(nt & 1) * 2 + 1]);
    }
}

// dual-A pass: acc += A0 @ W^T + A1 @ W^T   (B fragments loaded once)
__device__ __forceinline__ void gpassAA(const __nv_bfloat16* __restrict__ A0,
                                        const __nv_bfloat16* __restrict__ A1,
                                        const __nv_bfloat16* __restrict__ W,
                                        float acc[2][8][4], int row0, int col0, int lane)
{
    const int ar = lane & 15, ac = (lane >> 4) << 3;
    const int bj = ((lane >> 4) << 3) + (lane & 7);
    const int bk = ((lane >> 3) & 1) << 3;
    #pragma unroll
    for (int kt = 0; kt < 8; kt++) {
        const int k0 = kt * 16;
        u32 a0[2][4], a1[2][4];
        #pragma unroll
        for (int mt = 0; mt < 2; mt++) {
            u32 ad0 = (u32)__cvta_generic_to_shared(A0 + (row0 + mt * 16 + ar) * PA + k0 + ac);
            ldsm4(a0[mt][0], a0[mt][1], a0[mt][2], a0[mt][3], ad0);
            u32 ad1 = (u32)__cvta_generic_to_shared(A1 + (row0 + mt * 16 + ar) * PA + k0 + ac);
            ldsm4(a1[mt][0], a1[mt][1], a1[mt][2], a1[mt][3], ad1);
        }
        u32 b[4][4];
        #pragma unroll
        for (int np = 0; np < 4; np++) {
            u32 bd = (u32)__cvta_generic_to_shared(W + (col0 + np * 16 + bj) * PA + k0 + bk);
            ldsm4(b[np][0], b[np][1], b[np][2], b[np][3], bd);
        }
        #pragma unroll
        for (int mt = 0; mt < 2; mt++)
            #pragma unroll
            for (int nt = 0; nt < 8; nt++) {
                mma_bf16(acc[mt][nt], a0[mt][0], a0[mt][1], a0[mt][2], a0[mt][3],
                         b[nt >> 1][(nt & 1) * 2], b[nt >> 1][(nt & 1) * 2 + 1]);
                mma_bf16(acc[mt][nt], a1[mt][0], a1[mt][1], a1[mt][2], a1[mt][3],
                         b[nt >> 1][(nt & 1) * 2], b[nt >> 1][(nt & 1) * 2 + 1]);
            }
    }
}

// dual-B pass: acc += A @ W0^T + A @ W1^T   (A fragments loaded once)
__device__ __forceinline__ void gpassBB(const __nv_bfloat16* __restrict__ A,
                                        const __nv_bfloat16* __restrict__ W0,
                                        const __nv_bfloat16* __restrict__ W1,
                                        float acc[2][8][4], int row0, int col0, int lane)
{
    const int ar = lane & 15, ac = (lane >> 4) << 3;
    const int bj = ((lane >> 4) << 3) + (lane & 7);
    const int bk = ((lane >> 3) & 1) << 3;
    #pragma unroll
    for (int kt = 0; kt < 8; kt++) {
        const int k0 = kt * 16;
        u32 a[2][4];
        #pragma unroll
        for (int mt = 0; mt < 2; mt++) {
            u32 ad = (u32)__cvta_generic_to_shared(A + (row0 + mt * 16 + ar) * PA + k0 + ac);
            ldsm4(a[mt][0], a[mt][1], a[mt][2], a[mt][3], ad);
        }
        u32 b0[4][4], b1[4][4];
        #pragma unroll
        for (int np = 0; np < 4; np++) {
            u32 bd0 = (u32)__cvta_generic_to_shared(W0 + (col0 + np * 16 + bj) * PA + k0 + bk);
            ldsm4(b0[np][0], b0[np][1], b0[np][2], b0[np][3], bd0);
            u32 bd1 = (u32)__cvta_generic_to_shared(W1 + (col0 + np * 16 + bj) * PA + k0 + bk);
            ldsm4(b1[np][0], b1[np][1], b1[np][2], b1[np][3], bd1);
        }
        #pragma unroll
        for (int mt = 0; mt < 2; mt++)
            #pragma unroll
            for (int nt = 0; nt < 8; nt++) {
                mma_bf16(acc[mt][nt], a[mt][0], a[mt][1], a[mt][2], a[mt][3],
                         b0[nt >> 1][(nt & 1) * 2], b0[nt >> 1][(nt & 1) * 2 + 1]);
                mma_bf16(acc[mt][nt], a[mt][0], a[mt][1], a[mt][2], a[mt][3],
                         b1[nt >> 1][(nt & 1) * 2], b1[nt >> 1][(nt & 1) * 2 + 1]);
            }
    }
}

__device__ __forceinline__ void stage_w(char* smem, int off, const __nv_bfloat16* g) {
    const uint4* src = (const uint4*)g;
    #pragma unroll
    for (int it = 0; it < 8; it++) {
        int cc = threadIdx.x + it * 256;
        int j = cc >> 4, k8 = (cc & 15) * 8;
        *(uint4*)(smem + off + (j * PA + k8) * 2) = src[cc];
    }
}

__global__ __launch_bounds__(256, 1)
void precompute_mma(const float* __restrict__ x,     const float* __restrict__ mask,
                    const float* __restrict__ delta, const float* __restrict__ xlast,
                    const float* __restrict__ x_mean,
                    const float* __restrict__ w_dg_x, const float* __restrict__ b_dg_x,
                    const float* __restrict__ b_dg_h,
                    const float* __restrict__ b_z, const float* __restrict__ b_r,
                    const float* __restrict__ b_h)
{
    extern __shared__ char smem[];
    float* bias_s = (float*)(smem + SM_BIAS);
    __nv_bfloat16* Ahi = (__nv_bfloat16*)(smem + SM_AHI);
    __nv_bfloat16* Alo = (__nv_bfloat16*)(smem + SM_ALO);
    __nv_bfloat16* Mbf = (__nv_bfloat16*)(smem + SM_MBF);
    __nv_bfloat16* Whi = (__nv_bfloat16*)(smem + SM_WHI);
    __nv_bfloat16* Wlo = (__nv_bfloat16*)(smem + SM_WLO);

    const int tid  = threadIdx.x;
    const int lane = tid & 31;
    const int wrp  = tid >> 5;
    const int row0 = (wrp & 3) * 32;
    const int col0 = (wrp >> 2) * 64;
    const int brow = blockIdx.x * 128;
    const int b    = brow >> 8;
    const int g = lane >> 2, t = lane & 3;

    float acc[2][8][4];

    for (int idx = tid; idx < 128 * 128; idx += 256) {
        int r = idx >> 7, d = idx & 127;
        float v = delta[(size_t)(brow + r) * DD + d];
        __nv_bfloat16 hi = __float2bfloat16(v);
        Ahi[r * PA + d] = hi;
        Alo[r * PA + d] = __float2bfloat16(v - __bfloat162float(hi));
    }
    stage_w(smem, SM_WHI, g_Wbh + 6 * 16384);
    stage_w(smem, SM_WLO, g_Wbl + 6 * 16384);
    if (tid < 128) bias_s[tid] = b_dg_h[tid];
    __syncthreads();

    // ---- gamma_h: (Ahi+Alo)@Whi (shared B) + Ahi@Wlo ----
    #pragma unroll
    for (int mt = 0; mt < 2; mt++)
        #pragma unroll
        for (int nt = 0; nt < 8; nt++)
            #pragma unroll
            for (int q = 0; q < 4; q++) acc[mt][nt][q] = 0.0f;
    gpassAA(Ahi, Alo, Whi, acc, row0, col0, lane);
    gpass(Ahi, Wlo, acc, row0, col0, lane);
    #pragma unroll
    for (int mt = 0; mt < 2; mt++)
        #pragma unroll
        for (int nt = 0; nt < 8; nt++) {
            int j0 = col0 + nt * 8 + 2 * t;
            float2 bv = *(const float2*)&bias_s[j0];
            size_t r0g = (size_t)(brow + row0 + mt * 16 + g) * HH + j0;
            size_t r8g = r0g + (size_t)8 * HH;
            *(float2*)&g_gh[r0g] = make_float2(__expf(-fmaxf(acc[mt][nt][0] + bv.x, 0.0f)),
                                               __expf(-fmaxf(acc[mt][nt][1] + bv.y, 0.0f)));
            *(float2*)&g_gh[r8g] = make_float2(__expf(-fmaxf(acc[mt][nt][2] + bv.x, 0.0f)),
                                               __expf(-fmaxf(acc[mt][nt][3] + bv.y, 0.0f)));
        }
    __syncthreads();

    for (int idx = tid; idx < 128 * 128; idx += 256) {
        int r = idx >> 7, d = idx & 127;
        size_t gg = (size_t)(brow + r) * DD + d;
        float xv = x[gg], mv = mask[gg], dl = delta[gg], xl = xlast[gg];
        float gx = __expf(-fmaxf(fmaf(w_dg_x[d], dl, b_dg_x[d]), 0.0f));
        float xm = x_mean[b * DD + d];
        float xh = mv * xv + (1.0f - mv) * (gx * xl + (1.0f - gx) * xm);
        __nv_bfloat16 hi = __float2bfloat16(xh);
        Ahi[r * PA + d] = hi;
        Alo[r * PA + d] = __float2bfloat16(xh - __bfloat162float(hi));
        Mbf[r * PA + d] = __float2bfloat16(mv);
    }
    __syncthreads();

    const int wi[3] = {0, 2, 4};
    const int vi[3] = {1, 3, 5};
    const float* biases[3] = {b_z, b_r, b_h};
    float* outs[3] = {g_Xz, g_Xr, g_Xh};

    #pragma unroll 1
    for (int gate = 0; gate < 3; gate++) {
        stage_w(smem, SM_WHI, g_Wbh + wi[gate] * 16384);
        stage_w(smem, SM_WLO, g_Wbl + wi[gate] * 16384);
        if (tid < 128) bias_s[tid] = biases[gate][tid];
        __syncthreads();

        #pragma unroll
        for (int mt = 0; mt < 2; mt++)
            #pragma unroll
            for (int nt = 0; nt < 8; nt++)
                #pragma unroll
                for (int q = 0; q < 4; q++) acc[mt][nt][q] = 0.0f;

        // x_hat side: (Ahi+Alo)@Whi + Ahi@Wlo
        gpassAA(Ahi, Alo, Whi, acc, row0, col0, lane);
        gpass(Ahi, Wlo, acc, row0, col0, lane);

        // restage V hi/lo, then mask side with shared A frags
        __syncthreads();
        stage_w(smem, SM_WHI, g_Wbh + vi[gate] * 16384);
        stage_w(smem, SM_WLO, g_Wbl + vi[gate] * 16384);
        __syncthreads();
        gpassBB(Mbf, Whi, Wlo, acc, row0, col0, lane);

        float* obase = outs[gate];
        #pragma unroll
        for (int mt = 0; mt < 2; mt++)
            #pragma unroll
            for (int nt = 0; nt < 8; nt++) {
                int j0 = col0 + nt * 8 + 2 * t;
                float2 bv = *(const float2*)&bias_s[j0];
                size_t r0g = (size_t)(brow + row0 + mt * 16 + g) * HH + j0;
                size_t r8g = r0g + (size_t)8 * HH;
                *(float2*)&obase[r0g] = make_float2(acc[mt][nt][0] + bv.x, acc[mt][nt][1] + bv.y);
                *(float2*)&obase[r8g] = make_float2(acc[mt][nt][2] + bv.x, acc[mt][nt][3] + bv.y);
            }
        __syncthreads();
    }
}

// ---------------------------------------------------------------------------
// Kernel 2: recurrence (R11 verbatim — best known: 643 us).
// 128 CTAs x 256 threads, thread = (j, half). Uz/Ur in registers (64+64),
// Uh in smem; fused z+r loop; partials combined via smem xch; 4 barriers.
// ---------------------------------------------------------------------------
#define PUS 129
#define OFS_UZ  0
#define OFS_UR  16512
#define OFS_UH2 33024
#define OFS_HT  (OFS_UH2 + 16384)
#define OFS_RHT (OFS_HT + 512)
#define OFS_XZR (OFS_RHT + 512)
#define OFS_XH  (OFS_XZR + 1024)
#define SMEMB_FL (OFS_XH + 512)           // 51968 fl = 207872 B

__global__ __launch_bounds__(256, 1)
void recurrent_kernel(const float* __restrict__ hs0,
                      const float* __restrict__ Uz, const float* __restrict__ Ur,
                      const float* __restrict__ Uh,
                      const float* __restrict__ statics,
                      const float* __restrict__ W_out, const float* __restrict__ b_out,
                      float* __restrict__ out)
{
    extern __shared__ float sm[];
    float*  UzS  = sm + OFS_UZ;
    float*  UrS  = sm + OFS_UR;
    float2* Uh2  = (float2*)(sm + OFS_UH2);
    float*  hT   = sm + OFS_HT;
    float*  rhT  = sm + OFS_RHT;
    u64*    xchZR = (u64*)(sm + OFS_XZR);
    u64*    xchH  = (u64*)(sm + OFS_XH);

    const int tid  = threadIdx.x;
    const int j    = tid & 127;
    const bool h0  = tid < 128;
    const int k0   = h0 ? 0 : 64;
    const int kq0  = h0 ? 0 : 32;
    const int b0   = blockIdx.x * 4;

    for (int idx = tid; idx < HH * HH; idx += 256) {
        int jj = idx >> 7, k = idx & 127;
        UzS[k * PUS + jj] = Uz[idx];
        UrS[k * PUS + jj] = Ur[idx];
    }
    for (int idx = tid; idx < 64 * 128; idx += 256) {
        int kp = idx >> 7, jj = idx & 127;
        Uh2[kp * 128 + jj] = make_float2(Uh[jj * 128 + 2 * kp],
                                         Uh[jj * 128 + 2 * kp + 1]);
    }

    float hreg[4], cG[4], cXz[4], cXr[4], cXh[4], zg[4];
    if (h0) {
        #pragma unroll
        for (int r = 0; r < 4; r++) {
            hreg[r] = hs0[(b0 + r) * HH + j];
            int g = ((b0 + r) * TT) * HH + j;
            cG[r] = g_gh[g]; cXz[r] = g_Xz[g]; cXr[r] = g_Xr[g]; cXh[r] = g_Xh[g];
        }
    }
    __syncthreads();

    float uzr_[64], urr_[64];
    #pragma unroll
    for (int kk = 0; kk < 64; kk++) {
        uzr_[kk] = UzS[(k0 + kk) * PUS + j];
        urr_[kk] = UrS[(k0 + kk) * PUS + j];
    }

    u64 sz01 = 0, sz23 = 0, sr01 = 0, sr23 = 0, sh01 = 0, sh23 = 0;

    #pragma unroll 1
    for (int t = 0; t < TT; t++) {
        if (h0) {
            #pragma unroll
            for (int r = 0; r < 4; r++) hreg[r] *= cG[r];
            *(float4*)&hT[j * 4] = make_float4(hreg[0], hreg[1], hreg[2], hreg[3]);
        }
        __syncthreads();   // B1

        if (h0) {
            sz01 = packab(cXz[0], cXz[1]); sz23 = packab(cXz[2], cXz[3]);
            sr01 = packab(cXr[0], cXr[1]); sr23 = packab(cXr[2], cXr[3]);
            sh01 = packab(cXh[0], cXh[1]); sh23 = packab(cXh[2], cXh[3]);
            if (t + 1 < TT) {
                #pragma unroll
                for (int r = 0; r < 4; r++) {
                    int g = ((b0 + r) * TT + t + 1) * HH + j;
                    cG[r] = g_gh[g]; cXz[r] = g_Xz[g];
                    cXr[r] = g_Xr[g]; cXh[r] = g_Xh[g];
                }
            }
        }

        u64 az01 = 0, az23 = 0, ar01 = 0, ar23 = 0;
        #pragma unroll
        for (int kk = 0; kk < 64; kk++) {
            F4U2 hv; hv.f = *(const float4*)&hT[(k0 + kk) * 4];
            u64 uz2 = pack2(uzr_[kk]);
            u64 ur2 = pack2(urr_[kk]);
            az01 = ffma2(hv.u[0], uz2, az01);
            az23 = ffma2(hv.u[1], uz2, az23);
            ar01 = ffma2(hv.u[0], ur2, ar01);
            ar23 = ffma2(hv.u[1], ur2, ar23);
        }

        if (!h0) {
            xchZR[4 * j]     = az01;
            xchZR[4 * j + 1] = az23;
            xchZR[4 * j + 2] = ar01;
            xchZR[4 * j + 3] = ar23;
        }
        __syncthreads();   // B2

        if (h0) {
            u64 qz01 = xchZR[4 * j],     qz23 = xchZR[4 * j + 1];
            u64 qr01 = xchZR[4 * j + 2], qr23 = xchZR[4 * j + 3];
            float2 z01 = unpk(add2(add2(az01, qz01), sz01));
            float2 z23 = unpk(add2(add2(az23, qz23), sz23));
            float2 r01 = unpk(add2(add2(ar01, qr01), sr01));
            float2 r23 = unpk(add2(add2(ar23, qr23), sr23));
            zg[0] = 1.0f / (1.0f + __expf(-z01.x));
            zg[1] = 1.0f / (1.0f + __expf(-z01.y));
            zg[2] = 1.0f / (1.0f + __expf(-z23.x));
            zg[3] = 1.0f / (1.0f + __expf(-z23.y));
            float rg0 = 1.0f / (1.0f + __expf(-r01.x));
            float rg1 = 1.0f / (1.0f + __expf(-r01.y));
            float rg2 = 1.0f / (1.0f + __expf(-r23.x));
            float rg3 = 1.0f / (1.0f + __expf(-r23.y));
            *(float4*)&rhT[j * 4] = make_float4(rg0 * hreg[0], rg1 * hreg[1],
                                                rg2 * hreg[2], rg3 * hreg[3]);
        }
        __syncthreads();   // B3

        u64 ah01 = h0 ? sh01 : 0ull;
        u64 ah23 = h0 ? sh23 : 0ull;
        #pragma unroll 8
        for (int kp = kq0; kp < kq0 + 32; kp++) {
            int k4 = kp * 8;
            F4U2 re; re.f = *(const float4*)&rhT[k4];
            F4U2 ro; ro.f = *(const float4*)&rhT[k4 + 4];
            float2 u2 = Uh2[kp * 128 + j];
            u64 uhe = pack2(u2.x), uho = pack2(u2.y);
            ah01 = ffma2(re.u[0], uhe, ah01);
            ah23 = ffma2(re.u[1], uhe, ah23);
            ah01 = ffma2(ro.u[0], uho, ah01);
            ah23 = ffma2(ro.u[1], uho, ah23);
        }
        if (!h0) {
            xchH[2 * j]     = ah01;
            xchH[2 * j + 1] = ah23;
        }
        __syncthreads();   // B4

        if (h0) {
            float2 p01 = unpk(add2(ah01, xchH[2 * j]));
            float2 p23 = unpk(add2(ah23, xchH[2 * j + 1]));
            float pre[4] = {p01.x, p01.y, p23.x, p23.y};
            #pragma unroll
            for (int r = 0; r < 4; r++) {
                float ht = 2.0f / (1.0f + __expf(-2.0f * pre[r])) - 1.0f;
                hreg[r] = (1.0f - zg[r]) * hreg[r] + zg[r] * ht;
            }
        }
    }

    // ---- classifier ----
    __syncthreads();
    if (h0) {
        float wj = W_out[j];
        *(float4*)&hT[j * 4] = make_float4(hreg[0] * wj, hreg[1] * wj,
                                           hreg[2] * wj, hreg[3] * wj);
    }
    __syncthreads();
    for (int s = 64; s > 0; s >>= 1) {
        if (tid < s) {
            float4 a = *(const float4*)&hT[tid * 4];
            float4 c = *(const float4*)&hT[(tid + s) * 4];
            a.x += c.x; a.y += c.y; a.z += c.z; a.w += c.w;
            *(float4*)&hT[tid * 4] = a;
        }
        __syncthreads();
    }
    if (tid < 4) {
        float v = hT[tid];
        float sacc = 0.0f;
        #pragma unroll
        for (int s = 0; s < SS; s++)
            sacc = fmaf(statics[(b0 + tid) * SS + s], W_out[HH + s], sacc);
        out[b0 + tid] = v + sacc + b_out[0];
    }
}

// ---------------------------------------------------------------------------
// Launch
// ---------------------------------------------------------------------------
extern "C" void kernel_launch(void* const* d_in, const int* in_sizes, int n_in,
                              void* d_out, int out_size)
{
    const float* x       = (const float*)d_in[0];
    const float* statics = (const float*)d_in[1];
    const float* mask    = (const float*)d_in[2];
    const float* delta   = (const float*)d_in[3];
    const float* xlast   = (const float*)d_in[4];
    const float* x_mean  = (const float*)d_in[5];
    const float* hs0     = (const float*)d_in[6];
    const float* w_dg_x  = (const float*)d_in[7];
    const float* b_dg_x  = (const float*)d_in[8];
    const float* W_dg_h  = (const float*)d_in[9];
    const float* b_dg_h  = (const float*)d_in[10];
    const float* W_z = (const float*)d_in[11];
    const float* U_z = (const float*)d_in[12];
    const float* V_z = (const float*)d_in[13];
    const float* b_z = (const float*)d_in[14];
    const float* W_r = (const float*)d_in[15];
    const float* U_r = (const float*)d_in[16];
    const float* V_r = (const float*)d_in[17];
    const float* b_r = (const float*)d_in[18];
    const float* W_h = (const float*)d_in[19];
    const float* U_h = (const float*)d_in[20];
    const float* V_h = (const float*)d_in[21];
    const float* b_h = (const float*)d_in[22];
    const float* W_out = (const float*)d_in[23];
    const float* b_out = (const float*)d_in[24];
    float* out = (float*)d_out;

    const int smemB = SMEMB_FL * (int)sizeof(float);   // 207872
    cudaFuncSetAttribute(precompute_mma, cudaFuncAttributeMaxDynamicSharedMemorySize, SM_TOTAL);
    cudaFuncSetAttribute(recurrent_kernel, cudaFuncAttributeMaxDynamicSharedMemorySize, smemB);

    // two no-ops: ncu capture lands on precompute_mma (4th launch slot)
    noop_kernel<<<1, 32>>>();
    noop_kernel<<<1, 32>>>();
    convert_w<<<7, 256>>>(W_z, V_z, W_r, V_r, W_h, V_h, W_dg_h);
    precompute_mma<<<BT / 128, 256, SM_TOTAL>>>(x, mask, delta, xlast, x_mean,
                                                w_dg_x, b_dg_x, b_dg_h, b_z, b_r, b_h);
    recurrent_kernel<<<BB / 4, 256, smemB>>>(hs0, U_z, U_r, U_h,
                                             statics, W_out, b_out, out);
}